// round 3
// baseline (speedup 1.0000x reference)
#include <cuda_runtime.h>

// Conv2D 4096x4096 (*) 15x15 valid -> 4082x4082, fp32.
// R3: ky-pair diagonal reuse. (ky, i+1) and (ky+1, i) read the same input row,
// so per ky-pair we stream 9 shared windows instead of 2x8. Vector LDS.128
// wavefronts drop 600->355 per thread; weight rows load as broadcast LDS.128.
// L1 crossbar ~82us < FMA floor ~100us -> FMA-bound.

#define HGT 4096
#define WID 4096
#define KH  15
#define KW  15
#define OH  (HGT - KH + 1)   // 4082
#define OW  (WID - KW + 1)   // 4082

#define TW  128   // output tile width per block
#define TH  64    // output tile height per block
#define RX  4     // outputs per thread, x
#define RY  8     // outputs per thread, y
#define SW  144   // smem tile pitch in floats
#define SH  (TH + KH - 1)   // 78 rows

__global__ __launch_bounds__(256, 2)
void conv2d15_kernel(const float* __restrict__ x,
                     const float* __restrict__ w,
                     const float* __restrict__ bias,
                     float* __restrict__ out) {
    __shared__ float tile[SH][SW];
    __shared__ float swt[KH][16];         // weight rows padded to 16 floats

    const int tx  = threadIdx.x;          // 0..31
    const int ty  = threadIdx.y;          // 0..7
    const int tid = ty * 32 + tx;         // 0..255
    const int col0 = blockIdx.x * TW;
    const int row0 = blockIdx.y * TH;

    // weights, zero-padded to 16/row
    if (tid < KH * 16) {
        int r = tid / 16, c = tid % 16;
        swt[r][c] = (c < KW) ? w[r * KW + c] : 0.f;
    }

    // ---- load input tile (SH x SW floats) with float4, zero-fill OOB ----
    const int NV4 = SW / 4;               // 36 float4 per row
    for (int idx = tid; idx < SH * NV4; idx += 256) {
        int r  = idx / NV4;
        int c4 = idx - r * NV4;
        int gr = row0 + r;
        int gc = col0 + c4 * 4;
        float4 v;
        if (gr < HGT && gc + 3 < WID) {
            v = *(const float4*)(x + (size_t)gr * WID + gc);
        } else {
            v.x = (gr < HGT && gc + 0 < WID) ? x[(size_t)gr * WID + gc + 0] : 0.f;
            v.y = (gr < HGT && gc + 1 < WID) ? x[(size_t)gr * WID + gc + 1] : 0.f;
            v.z = (gr < HGT && gc + 2 < WID) ? x[(size_t)gr * WID + gc + 2] : 0.f;
            v.w = (gr < HGT && gc + 3 < WID) ? x[(size_t)gr * WID + gc + 3] : 0.f;
        }
        *(float4*)&tile[r][c4 * 4] = v;
    }
    __syncthreads();

    float acc[RY][RX];
    #pragma unroll
    for (int i = 0; i < RY; i++)
        #pragma unroll
        for (int j = 0; j < RX; j++)
            acc[i][j] = 0.f;

    const int txc = tx * RX;              // first output col inside tile (16B aligned)
    const int tyr = ty * RY;              // first output row inside tile

    // ---- ky-pair loop: ky = 2*kp, 2*kp+1 share 9 input rows ----
    #pragma unroll 1
    for (int kp = 0; kp < KH / 2; kp++) { // 7 pairs (ky 0..13)
        // weight rows: broadcast LDS.128 (uniform address -> 1 wavefront each)
        float wa[16], wb[16];
        {
            const float4* pa = (const float4*)&swt[2 * kp][0];
            const float4* pb = (const float4*)&swt[2 * kp + 1][0];
            #pragma unroll
            for (int q = 0; q < 4; q++) {
                float4 va = pa[q], vb = pb[q];
                wa[q*4+0]=va.x; wa[q*4+1]=va.y; wa[q*4+2]=va.z; wa[q*4+3]=va.w;
                wb[q*4+0]=vb.x; wb[q*4+1]=vb.y; wb[q*4+2]=vb.z; wb[q*4+3]=vb.w;
            }
        }
        #pragma unroll
        for (int t = 0; t < RY + 1; t++) {   // 9 shared rows
            const int r = tyr + 2 * kp + t;
            float win[20];
            const float4* p = (const float4*)&tile[r][txc];
            #pragma unroll
            for (int q = 0; q < 5; q++) {
                float4 v = p[q];
                win[q*4+0]=v.x; win[q*4+1]=v.y; win[q*4+2]=v.z; win[q*4+3]=v.w;
            }
            if (t < RY) {        // (ky=2kp, i=t)
                #pragma unroll
                for (int kx = 0; kx < KW; kx++) {
                    const float wv = wa[kx];
                    #pragma unroll
                    for (int j = 0; j < RX; j++)
                        acc[t][j] = fmaf(wv, win[kx + j], acc[t][j]);
                }
            }
            if (t > 0) {         // (ky=2kp+1, i=t-1)
                #pragma unroll
                for (int kx = 0; kx < KW; kx++) {
                    const float wv = wb[kx];
                    #pragma unroll
                    for (int j = 0; j < RX; j++)
                        acc[t - 1][j] = fmaf(wv, win[kx + j], acc[t - 1][j]);
                }
            }
        }
    }

    // ---- solo ky = 14 ----
    {
        float wa[16];
        const float4* pa = (const float4*)&swt[KH - 1][0];
        #pragma unroll
        for (int q = 0; q < 4; q++) {
            float4 va = pa[q];
            wa[q*4+0]=va.x; wa[q*4+1]=va.y; wa[q*4+2]=va.z; wa[q*4+3]=va.w;
        }
        #pragma unroll
        for (int t = 0; t < RY; t++) {
            const int r = tyr + (KH - 1) + t;
            float win[20];
            const float4* p = (const float4*)&tile[r][txc];
            #pragma unroll
            for (int q = 0; q < 5; q++) {
                float4 v = p[q];
                win[q*4+0]=v.x; win[q*4+1]=v.y; win[q*4+2]=v.z; win[q*4+3]=v.w;
            }
            #pragma unroll
            for (int kx = 0; kx < KW; kx++) {
                const float wv = wa[kx];
                #pragma unroll
                for (int j = 0; j < RX; j++)
                    acc[t][j] = fmaf(wv, win[kx + j], acc[t][j]);
            }
        }
    }

    // ---- store with bias, guarded at right/bottom edges ----
    const float b = bias[0];
    const int ocol = col0 + txc;
    #pragma unroll
    for (int i = 0; i < RY; i++) {
        const int orow = row0 + tyr + i;
        if (orow < OH) {
            #pragma unroll
            for (int j = 0; j < RX; j++) {
                const int oc = ocol + j;
                if (oc < OW)
                    out[(size_t)orow * OW + oc] = acc[i][j] + b;
            }
        }
    }
}

extern "C" void kernel_launch(void* const* d_in, const int* in_sizes, int n_in,
                              void* d_out, int out_size) {
    const float* x    = (const float*)d_in[0];
    const float* w    = (const float*)d_in[1];
    const float* bias = (const float*)d_in[2];
    float* out        = (float*)d_out;

    dim3 block(32, 8, 1);
    dim3 grid((OW + TW - 1) / TW, (OH + TH - 1) / TH, 1);  // (32, 64)
    conv2d15_kernel<<<grid, block>>>(x, w, bias, out);
}